// round 8
// baseline (speedup 1.0000x reference)
#include <cuda_runtime.h>
#include <cstdint>

#define N_ROWS 1024
#define M_ROWS 1024
#define DIM    512
#define BT     64
#define KC     32
#define NCH    (DIM / KC)   // 16 chunks
#define PADK   36           // row stride 144B; stride-16 rows -> conflict-free LDS.128

using u64 = unsigned long long;

__device__ float g_zn[N_ROWS];     // ||z_n||^2
__device__ float g_zprn[M_ROWS];   // ||zpr_m||^2

// packed fp32 ops (sm_100+), each = 1 issue slot, 2 fma-pipe slots
#define FMA2(d, a, b, c) asm("fma.rn.f32x2 %0, %1, %2, %3;" : "=l"(d) : "l"(a), "l"(b), "l"(c))
#define FMA2ACC(acc, a, b) asm("fma.rn.f32x2 %0, %1, %2, %0;" : "+l"(acc) : "l"(a), "l"(b))
#define ADD2ACC(acc, x)    asm("add.rn.f32x2 %0, %0, %1;"     : "+l"(acc) : "l"(x))

__device__ __forceinline__ void upk(float& x, float& y, u64 v) {
    asm("mov.b64 {%0, %1}, %2;" : "=f"(x), "=f"(y) : "l"(v));
}

__device__ __forceinline__ void cp16(uint32_t smem, const void* g) {
    asm volatile("cp.async.cg.shared.global [%0], [%1], 16;" :: "r"(smem), "l"(g));
}
#define CP_COMMIT() asm volatile("cp.async.commit_group;")
#define CP_WAIT0()  asm volatile("cp.async.wait_group 0;")

// One warp per row: squared-norm.
__global__ void norms_kernel(const float* __restrict__ z, const float* __restrict__ zpr) {
    int warp = (blockIdx.x * blockDim.x + threadIdx.x) >> 5;
    int lane = threadIdx.x & 31;
    if (warp >= N_ROWS + M_ROWS) return;
    const float* src = (warp < N_ROWS) ? (z + (size_t)warp * DIM)
                                       : (zpr + (size_t)(warp - N_ROWS) * DIM);
    float q = 0.0f;
    #pragma unroll
    for (int i = 0; i < DIM / 32; ++i) {
        float v = src[i * 32 + lane];
        q = fmaf(v, v, q);
    }
    #pragma unroll
    for (int o = 16; o; o >>= 1) q += __shfl_xor_sync(0xffffffffu, q, o);
    if (lane == 0) {
        if (warp < N_ROWS) g_zn[warp] = q;
        else               g_zprn[warp - N_ROWS] = q;
    }
}

// All-packed inner loop on d = a - b:
//   l1 += |d| (FMA2 diff, LOP3 abs, ADD2 acc);  s2 += d*d (FMA2)
//   l2 = sqrt(s2);  dp = (|a|^2 + |b|^2 - s2) / 2
// out[m][n][3] = {l1, l2, dp}
__global__ __launch_bounds__(256, 2)
void pair_kernel(const float* __restrict__ z,
                 const float* __restrict__ zpr,
                 float* __restrict__ out) {
    __shared__ __align__(16) float as[2][BT][PADK];
    __shared__ __align__(16) float bs[2][BT][PADK];

    const int tid = threadIdx.x;
    const int tx = tid & 15;    // n rows: tx + 16*i
    const int ty = tid >> 4;    // m rows: ty + 16*j
    const int n0 = blockIdx.x * BT;
    const int m0 = blockIdx.y * BT;

    const int scol = (tid & 7) * 4;
    const int srow = tid >> 3;
    const float* gz  = z   + (size_t)(n0 + srow) * DIM + scol;
    const float* gzp = zpr + (size_t)(m0 + srow) * DIM + scol;

    uint32_t sa0 = (uint32_t)__cvta_generic_to_shared(&as[0][srow][scol]);
    uint32_t sa1 = (uint32_t)__cvta_generic_to_shared(&as[0][srow + 32][scol]);
    uint32_t sb0 = (uint32_t)__cvta_generic_to_shared(&bs[0][srow][scol]);
    uint32_t sb1 = (uint32_t)__cvta_generic_to_shared(&bs[0][srow + 32][scol]);
    const uint32_t BUFOFF = (uint32_t)(BT * PADK * sizeof(float));

    const u64 ABS  = 0x7fffffff7fffffffull;
    const u64 NEG1 = 0xBF800000BF800000ull;   // packed (-1.0f, -1.0f)

    u64 s2a[4][4];   // packed sum of d^2
    u64 l1a[4][4];   // packed sum of |d|
    #pragma unroll
    for (int i = 0; i < 4; ++i)
        #pragma unroll
        for (int j = 0; j < 4; ++j) { s2a[i][j] = 0ull; l1a[i][j] = 0ull; }

    // prefetch chunk 0 into buffer 0
    cp16(sa0, gz);            cp16(sa1, gz  + (size_t)32 * DIM);
    cp16(sb0, gzp);           cp16(sb1, gzp + (size_t)32 * DIM);
    CP_COMMIT();

    for (int c = 0; c < NCH; ++c) {
        CP_WAIT0();
        __syncthreads();

        if (c + 1 < NCH) {
            uint32_t o = ((c + 1) & 1) * BUFOFF;
            const float* pz  = gz  + (c + 1) * KC;
            const float* pzp = gzp + (c + 1) * KC;
            cp16(sa0 + o, pz);   cp16(sa1 + o, pz  + (size_t)32 * DIM);
            cp16(sb0 + o, pzp);  cp16(sb1 + o, pzp + (size_t)32 * DIM);
            CP_COMMIT();
        }

        const int s = c & 1;
        #pragma unroll
        for (int kk = 0; kk < KC; kk += 4) {
            u64 a[4][2], b[4][2];
            #pragma unroll
            for (int i = 0; i < 4; ++i) {
                ulonglong2 t = *(const ulonglong2*)&as[s][tx + 16 * i][kk];  // LDS.128
                a[i][0] = t.x; a[i][1] = t.y;
            }
            #pragma unroll
            for (int j = 0; j < 4; ++j) {
                ulonglong2 t = *(const ulonglong2*)&bs[s][ty + 16 * j][kk];  // broadcast
                b[j][0] = t.x; b[j][1] = t.y;
            }
            #pragma unroll
            for (int i = 0; i < 4; ++i) {
                #pragma unroll
                for (int j = 0; j < 4; ++j) {
                    u64 d0, d1;
                    FMA2(d0, b[j][0], NEG1, a[i][0]);   // d = a - b (packed, fma)
                    FMA2(d1, b[j][1], NEG1, a[i][1]);
                    u64 ad0 = d0 & ABS;                 // |d| (2x LOP3, alu)
                    u64 ad1 = d1 & ABS;
                    ADD2ACC(l1a[i][j], ad0);            // l1 += |d|
                    ADD2ACC(l1a[i][j], ad1);
                    FMA2ACC(s2a[i][j], ad0, ad0);       // s2 += d^2
                    FMA2ACC(s2a[i][j], ad1, ad1);
                }
            }
        }
        __syncthreads();
    }

    // epilogue
    float zn[4], pn[4];
    #pragma unroll
    for (int i = 0; i < 4; ++i) zn[i] = g_zn[n0 + tx + 16 * i];
    #pragma unroll
    for (int j = 0; j < 4; ++j) pn[j] = g_zprn[m0 + ty + 16 * j];

    #pragma unroll
    for (int j = 0; j < 4; ++j) {
        #pragma unroll
        for (int i = 0; i < 4; ++i) {
            float l1lo, l1hi, s2lo, s2hi;
            upk(l1lo, l1hi, l1a[i][j]);
            upk(s2lo, s2hi, s2a[i][j]);
            float s2 = s2lo + s2hi;
            float l1 = l1lo + l1hi;
            float l2 = sqrtf(s2);
            float dp = 0.5f * (zn[i] + pn[j] - s2);
            int n = n0 + tx + 16 * i;
            int m = m0 + ty + 16 * j;
            float* o = out + ((size_t)m * N_ROWS + n) * 3;
            o[0] = l1;
            o[1] = l2;
            o[2] = dp;
        }
    }
}

extern "C" void kernel_launch(void* const* d_in, const int* in_sizes, int n_in,
                              void* d_out, int out_size) {
    const float* z   = (const float*)d_in[0];
    const float* zpr = (const float*)d_in[1];
    float* out = (float*)d_out;

    norms_kernel<<<(N_ROWS + M_ROWS) * 32 / 256, 256>>>(z, zpr);

    dim3 grid(N_ROWS / BT, M_ROWS / BT);
    pair_kernel<<<grid, 256>>>(z, zpr, out);
}

// round 9
// speedup vs baseline: 1.1866x; 1.1866x over previous
#include <cuda_runtime.h>
#include <cstdint>

#define N_ROWS 1024
#define M_ROWS 1024
#define DIM    512
#define BTN    32           // tile edge (n and m)
#define KC     32
#define NCH    (DIM / KC)   // 16 chunks
#define PADK   36           // row stride 144B; stride-8 rows -> conflict-free LDS.128

using u64 = unsigned long long;

__device__ float g_zn[N_ROWS];     // ||z_n||^2
__device__ float g_zprn[M_ROWS];   // ||zpr_m||^2
__device__ float g_zs[N_ROWS];     // sum z_n
__device__ float g_zprs[M_ROWS];   // sum zpr_m

// packed fp32 fma: 1 issue slot, 2 fma-pipe slots
#define FMA2ACC(acc, a, b) asm("fma.rn.f32x2 %0, %1, %2, %0;" : "+l"(acc) : "l"(a), "l"(b))

__device__ __forceinline__ void upk(float& x, float& y, u64 v) {
    asm("mov.b64 {%0, %1}, %2;" : "=f"(x), "=f"(y) : "l"(v));
}

__device__ __forceinline__ void cp16(uint32_t smem, const void* g) {
    asm volatile("cp.async.cg.shared.global [%0], [%1], 16;" :: "r"(smem), "l"(g));
}
#define CP_COMMIT() asm volatile("cp.async.commit_group;")
#define CP_WAIT0()  asm volatile("cp.async.wait_group 0;")

// One warp per row: sum + squared-norm.
__global__ void norms_kernel(const float* __restrict__ z, const float* __restrict__ zpr) {
    int warp = (blockIdx.x * blockDim.x + threadIdx.x) >> 5;
    int lane = threadIdx.x & 31;
    if (warp >= N_ROWS + M_ROWS) return;
    const float* src = (warp < N_ROWS) ? (z + (size_t)warp * DIM)
                                       : (zpr + (size_t)(warp - N_ROWS) * DIM);
    float s = 0.0f, q = 0.0f;
    #pragma unroll
    for (int i = 0; i < DIM / 32; ++i) {
        float v = src[i * 32 + lane];
        s += v;
        q = fmaf(v, v, q);
    }
    #pragma unroll
    for (int o = 16; o; o >>= 1) {
        s += __shfl_xor_sync(0xffffffffu, s, o);
        q += __shfl_xor_sync(0xffffffffu, q, o);
    }
    if (lane == 0) {
        if (warp < N_ROWS) { g_zn[warp] = q; g_zs[warp] = s; }
        else               { g_zprn[warp - N_ROWS] = q; g_zprs[warp - N_ROWS] = s; }
    }
}

// Per pair: dp via packed FFMA2; lm = sum max(a,b) (FMNMX alu + FADD fma);
// l1 = 2*lm - Sa - Sb; l2 = sqrt(|a|^2+|b|^2-2dp). out[m][n][3] = {l1, l2, dp}
__global__ __launch_bounds__(128, 5)
void pair_kernel(const float* __restrict__ z,
                 const float* __restrict__ zpr,
                 float* __restrict__ out) {
    __shared__ __align__(16) float as[2][BTN][PADK];
    __shared__ __align__(16) float bs[2][BTN][PADK];

    const int tid = threadIdx.x;
    const int tx = tid & 7;     // n rows: tx + 8*i, i<4
    const int ty = tid >> 3;    // m rows: ty + 16*j, j<2
    const int n0 = blockIdx.x * BTN;
    const int m0 = blockIdx.y * BTN;

    // staging: 128 threads x 2 cp16 per array = 32 rows x 32 k
    const int scol = (tid & 7) * 4;
    const int srow = tid >> 3;            // 0..15, plus +16
    const float* gz  = z   + (size_t)(n0 + srow) * DIM + scol;
    const float* gzp = zpr + (size_t)(m0 + srow) * DIM + scol;

    uint32_t sa0 = (uint32_t)__cvta_generic_to_shared(&as[0][srow][scol]);
    uint32_t sa1 = (uint32_t)__cvta_generic_to_shared(&as[0][srow + 16][scol]);
    uint32_t sb0 = (uint32_t)__cvta_generic_to_shared(&bs[0][srow][scol]);
    uint32_t sb1 = (uint32_t)__cvta_generic_to_shared(&bs[0][srow + 16][scol]);
    const uint32_t BUFOFF = (uint32_t)(BTN * PADK * sizeof(float));

    u64   dpn[4][2];   // packed dot accumulators
    float lm[4][2];    // sum of max(a,b)
    #pragma unroll
    for (int i = 0; i < 4; ++i)
        #pragma unroll
        for (int j = 0; j < 2; ++j) { dpn[i][j] = 0ull; lm[i][j] = 0.0f; }

    // prefetch chunk 0 into buffer 0
    cp16(sa0, gz);            cp16(sa1, gz  + (size_t)16 * DIM);
    cp16(sb0, gzp);           cp16(sb1, gzp + (size_t)16 * DIM);
    CP_COMMIT();

    for (int c = 0; c < NCH; ++c) {
        CP_WAIT0();
        __syncthreads();

        if (c + 1 < NCH) {
            uint32_t o = ((c + 1) & 1) * BUFOFF;
            const float* pz  = gz  + (c + 1) * KC;
            const float* pzp = gzp + (c + 1) * KC;
            cp16(sa0 + o, pz);   cp16(sa1 + o, pz  + (size_t)16 * DIM);
            cp16(sb0 + o, pzp);  cp16(sb1 + o, pzp + (size_t)16 * DIM);
            CP_COMMIT();
        }

        const int s = c & 1;
        #pragma unroll
        for (int kk = 0; kk < KC; kk += 4) {
            u64 a[4][2], b[2][2];
            float af[4][4], bf[2][4];
            #pragma unroll
            for (int i = 0; i < 4; ++i) {
                ulonglong2 t = *(const ulonglong2*)&as[s][tx + 8 * i][kk];   // LDS.128
                a[i][0] = t.x; a[i][1] = t.y;
                upk(af[i][0], af[i][1], t.x);
                upk(af[i][2], af[i][3], t.y);
            }
            #pragma unroll
            for (int j = 0; j < 2; ++j) {
                ulonglong2 t = *(const ulonglong2*)&bs[s][ty + 16 * j][kk];  // broadcast
                b[j][0] = t.x; b[j][1] = t.y;
                upk(bf[j][0], bf[j][1], t.x);
                upk(bf[j][2], bf[j][3], t.y);
            }
            #pragma unroll
            for (int i = 0; i < 4; ++i) {
                #pragma unroll
                for (int j = 0; j < 2; ++j) {
                    FMA2ACC(dpn[i][j], a[i][0], b[j][0]);     // 2 elems / issue
                    FMA2ACC(dpn[i][j], a[i][1], b[j][1]);
                    lm[i][j] += fmaxf(af[i][0], bf[j][0]);    // FMNMX(alu)+FADD(fma)
                    lm[i][j] += fmaxf(af[i][1], bf[j][1]);
                    lm[i][j] += fmaxf(af[i][2], bf[j][2]);
                    lm[i][j] += fmaxf(af[i][3], bf[j][3]);
                }
            }
        }
        __syncthreads();
    }

    // epilogue
    float zn[4], zs[4], pn[2], ps[2];
    #pragma unroll
    for (int i = 0; i < 4; ++i) { zn[i] = g_zn[n0 + tx + 8 * i]; zs[i] = g_zs[n0 + tx + 8 * i]; }
    #pragma unroll
    for (int j = 0; j < 2; ++j) { pn[j] = g_zprn[m0 + ty + 16 * j]; ps[j] = g_zprs[m0 + ty + 16 * j]; }

    #pragma unroll
    for (int j = 0; j < 2; ++j) {
        #pragma unroll
        for (int i = 0; i < 4; ++i) {
            float dlo, dhi;
            upk(dlo, dhi, dpn[i][j]);
            float dp = dlo + dhi;
            float l1 = 2.0f * lm[i][j] - zs[i] - ps[j];
            float l2 = sqrtf(fmaxf(zn[i] + pn[j] - 2.0f * dp, 0.0f));
            int n = n0 + tx + 8 * i;
            int m = m0 + ty + 16 * j;
            float* o = out + ((size_t)m * N_ROWS + n) * 3;
            o[0] = l1;
            o[1] = l2;
            o[2] = dp;
        }
    }
}

extern "C" void kernel_launch(void* const* d_in, const int* in_sizes, int n_in,
                              void* d_out, int out_size) {
    const float* z   = (const float*)d_in[0];
    const float* zpr = (const float*)d_in[1];
    float* out = (float*)d_out;

    norms_kernel<<<(N_ROWS + M_ROWS) * 32 / 256, 256>>>(z, zpr);

    dim3 grid(N_ROWS / BTN, M_ROWS / BTN);
    pair_kernel<<<grid, 128>>>(z, zpr, out);
}